// round 2
// baseline (speedup 1.0000x reference)
#include <cuda_runtime.h>
#include <cuda_bf16.h>
#include <cstdint>

// Problem constants (fixed by the dataset): B=64, T=12, C=64, SIDE=32, S2=1024.
#define PB   64
#define PT   12
#define PC   64
#define PS2  1024
#define ROWS (PB * PC)        // 4096 (b,c) rows in the last-T slice
#define ROWS_PER_RBLK 16      // reduce: rows per block

// Scratch (no device allocation allowed): per-cell nonzero flags + int32 poi.
__device__ __align__(16) int g_nz[PS2];
__device__ __align__(16) int g_poi[PS2];

// Kernel 0: zero flags + load poi_index with dtype auto-detect (int32 vs int64).
// JAX under default config silently narrows jnp.int64 -> int32; handle both.
// 1 block x 1024 threads.
__global__ void init_kernel(const int* __restrict__ poi_words) {
    __shared__ int odd_nonzero;
    const int t = threadIdx.x;
    if (t == 0) odd_nonzero = 0;
    g_nz[t] = 0;
    const int w = poi_words[t];
    __syncthreads();
    if ((t & 1) && w != 0) atomicOr(&odd_nonzero, 1);
    __syncthreads();
    if (odd_nonzero) {
        // genuine int32 buffer: word t IS poi[t]
        g_poi[t] = w;
    } else {
        // int64 buffer: value t lives at word 2t (little-endian, values < 2^31)
        g_poi[t] = poi_words[2 * t];
    }
}

// Kernel 1: column-OR reduce of mask slice m[:, T-1] over all 4096 rows.
// Each block: 256 threads x int4 covers all 1024 columns; loops 16 rows.
__global__ void reduce_kernel(const int* __restrict__ m) {
    const int t = threadIdx.x;            // 0..255
    const int row0 = blockIdx.x * ROWS_PER_RBLK;
    int4 acc = make_int4(0, 0, 0, 0);
#pragma unroll
    for (int i = 0; i < ROWS_PER_RBLK; i++) {
        const int row = row0 + i;
        const int b = row >> 6;
        const int c = row & 63;
        const size_t base = ((size_t)(b * PT + (PT - 1)) * PC + c) * PS2;
        const int4 v = *(const int4*)(m + base + 4 * t);
        acc.x |= v.x; acc.y |= v.y; acc.z |= v.z; acc.w |= v.w;
    }
    // Only touch flags that are actually nonzero (halves atomic traffic:
    // even cells are forced-zero by the reference's cell_keep).
    if (acc.x) atomicOr(&g_nz[4 * t + 0], 1);
    if (acc.y) atomicOr(&g_nz[4 * t + 1], 1);
    if (acc.z) atomicOr(&g_nz[4 * t + 2], 1);
    if (acc.w) atomicOr(&g_nz[4 * t + 3], 1);
}

// Kernel 2: out[row, s] = data[row, s] + (empty[s] ? data[row, poi[s]] : 0).
// One block per (b,c) row; row staged in shared so the random gather is an LDS.
__global__ void apply_kernel(const float* __restrict__ d, float* __restrict__ out) {
    __shared__ float row_s[PS2];
    const int t = threadIdx.x;            // 0..255
    const int row = blockIdx.x;           // 0..4095
    const int b = row >> 6;
    const int c = row & 63;
    const size_t base = ((size_t)(b * PT + (PT - 1)) * PC + c) * PS2;

    float4 v = *(const float4*)(d + base + 4 * t);
    ((float4*)row_s)[t] = v;

    const int4 nz = ((const int4*)g_nz)[t];
    const int4 pi = ((const int4*)g_poi)[t];
    __syncthreads();

    if (!nz.x) v.x += row_s[pi.x];
    if (!nz.y) v.y += row_s[pi.y];
    if (!nz.z) v.z += row_s[pi.z];
    if (!nz.w) v.w += row_s[pi.w];

    ((float4*)out)[(size_t)row * (PS2 / 4) + t] = v;
}

extern "C" void kernel_launch(void* const* d_in, const int* in_sizes, int n_in,
                              void* d_out, int out_size) {
    const float* d   = (const float*)d_in[0];
    const int*   m   = (const int*)d_in[1];
    const int*   poi = (const int*)d_in[2];   // int32 or int64 words, auto-detected
    // d_in[3] = side (constant 32), unused.
    float* out = (float*)d_out;

    init_kernel<<<1, PS2>>>(poi);
    reduce_kernel<<<ROWS / ROWS_PER_RBLK, 256>>>(m);
    apply_kernel<<<ROWS, 256>>>(d, out);
}